// round 3
// baseline (speedup 1.0000x reference)
#include <cuda_runtime.h>
#include <cuda_bf16.h>
#include <cstdint>

// ---------------------------------------------------------------------------
// Problem:
//   Ec : (128 chan, 256 s, 3 l, 128 d) f32
//   W1 : (6,128,128,1,128)  W2 : (5,128,128,2,128)  W3 : (5,128,128,3,128)
//   b1 : (6,128) b2 : (5,128) b3 : (5,128)
//   out: (128 o, 256 s, 1, 16 k) f32
// 33 conv maps: z<18 -> h=1 (kl=z/3, p=z%3); z<28 -> h=2; else h=3.
// GEMM per map: out[o,s] = sum_{a,c,d} Ec[a,s,p+c,d] * W[kl,o,a,c,d]
//   M=256(s) N=128(o) K=128*h*128.  Split-K: chunks of 32 (a,c) pairs (K=4096).
// bf16 hi/lo 3-GEMM split for fp32-grade accuracy on tensor cores (mma.sync —
// the harness's virtual arch is compute_103, so tcgen05 is unavailable).
// ---------------------------------------------------------------------------

#define NMAPS 33
#define SLOT_STRIDE 12            // max chunks per map = 4*h <= 12
__device__ float g_part[NMAPS * SLOT_STRIDE * 128 * 256];

#define PITCH 80                  // smem row pitch (bytes): 64B data + 16B pad
#define STAGE_BYTES (4 * 128 * PITCH)   // Ahi,Alo,Bhi,Blo tiles of 128 rows
#define OFF_AHI 0
#define OFF_ALO (128 * PITCH)
#define OFF_BHI (2 * 128 * PITCH)
#define OFF_BLO (3 * 128 * PITCH)
#define SMEM_BYTES (2 * STAGE_BYTES)    // double buffered = 81920 B

// ---------------------------------------------------------------------------
__device__ __forceinline__ uint32_t smem_u32(const void* p) {
    uint32_t r;
    asm("{ .reg .u64 t; cvta.to.shared.u64 t, %1; cvt.u32.u64 %0, t; }"
        : "=r"(r) : "l"(p));
    return r;
}

__device__ __forceinline__ void ldm4(uint32_t (&r)[4], uint32_t addr) {
    asm volatile("ldmatrix.sync.aligned.m8n8.x4.shared.b16 {%0,%1,%2,%3}, [%4];"
        : "=r"(r[0]), "=r"(r[1]), "=r"(r[2]), "=r"(r[3]) : "r"(addr));
}

__device__ __forceinline__ void mma_bf16(float (&d)[4], const uint32_t (&a)[4],
                                         uint32_t b0, uint32_t b1) {
    asm volatile(
        "mma.sync.aligned.m16n8k16.row.col.f32.bf16.bf16.f32 "
        "{%0,%1,%2,%3}, {%4,%5,%6,%7}, {%8,%9}, {%0,%1,%2,%3};"
        : "+f"(d[0]), "+f"(d[1]), "+f"(d[2]), "+f"(d[3])
        : "r"(a[0]), "r"(a[1]), "r"(a[2]), "r"(a[3]), "r"(b0), "r"(b1));
}

// f32x4 -> bf16 hi pair + bf16 lo (residual) pair
__device__ __forceinline__ void cvt2(float4 v, uint2& hi, uint2& lo) {
    __nv_bfloat162 h01 = __floats2bfloat162_rn(v.x, v.y);
    __nv_bfloat162 h23 = __floats2bfloat162_rn(v.z, v.w);
    float2 f01 = __bfloat1622float2(h01);
    float2 f23 = __bfloat1622float2(h23);
    __nv_bfloat162 l01 = __floats2bfloat162_rn(v.x - f01.x, v.y - f01.y);
    __nv_bfloat162 l23 = __floats2bfloat162_rn(v.z - f23.x, v.w - f23.y);
    hi.x = *reinterpret_cast<uint32_t*>(&h01);
    hi.y = *reinterpret_cast<uint32_t*>(&h23);
    lo.x = *reinterpret_cast<uint32_t*>(&l01);
    lo.y = *reinterpret_cast<uint32_t*>(&l23);
}

// ---------------------------------------------------------------------------
// GEMM: grid (212, 2).  blockIdx.x = chunk job, blockIdx.y = s-tile (128).
// Each job: one map z, 32 (a,c) pairs (K = 4096), full o (128).
// ---------------------------------------------------------------------------
__global__ __launch_bounds__(256, 1)
void vrtconv_gemm(const float* __restrict__ Ec, const float* __restrict__ W1,
                  const float* __restrict__ W2, const float* __restrict__ W3)
{
    extern __shared__ char smem[];
    const int tid  = threadIdx.x;
    const int lane = tid & 31;
    const int wid  = tid >> 5;
    const int wm   = wid & 3;      // 4 m-warps (32 s each)
    const int wn   = wid >> 2;     // 2 n-warps (64 o each)
    const uint32_t sb = smem_u32(smem);

    // job decode
    const int j = blockIdx.x;
    int z, chunk, h;
    if (j < 72)       { z = j >> 2;                 chunk = j & 3;   h = 1; }
    else if (j < 152) { int t = j - 72;  z = 18 + (t >> 3); chunk = t & 7;  h = 2; }
    else              { int t = j - 152; z = 28 + t / 12;   chunk = t % 12; h = 3; }

    int kl, p; const float* W;
    if (h == 1)      { kl = z / 3;        p = z % 3;        W = W1; }
    else if (h == 2) { kl = (z - 18) >> 1; p = (z - 18) & 1; W = W2; }
    else             { kl = z - 28;       p = 0;            W = W3; }

    const int s_base = blockIdx.y * 128;
    const size_t oStride = (size_t)16384 * h;        // o-row stride in W (f32)
    const float* Wk = W + (size_t)kl * 2097152 * (size_t)h;

    float acc[2][8][4];
    #pragma unroll
    for (int a = 0; a < 2; ++a)
        #pragma unroll
        for (int b = 0; b < 8; ++b)
            #pragma unroll
            for (int c = 0; c < 4; ++c) acc[a][b][c] = 0.0f;

    float4 ra[4], rb[4];   // prefetch registers (stage = 128 rows x 32 f32)

    auto ldgl = [&](int st) {
        const int q  = chunk * 32 + (st >> 2);       // (a,c) pair index
        const int a  = q / h, c = q - a * h;
        const int d0 = (st & 3) * 32;
        const float* Ab = Ec + (size_t)a * 98304 + (size_t)(p + c) * 128
                             + (size_t)s_base * 384 + d0;
        const float* Bb = Wk + (size_t)a * (h * 128) + (size_t)c * 128 + d0;
        #pragma unroll
        for (int i = 0; i < 4; ++i) {
            const int flat = i * 256 + tid;
            const int row = flat >> 3, c4 = flat & 7;
            ra[i] = *reinterpret_cast<const float4*>(Ab + (size_t)row * 384 + c4 * 4);
            rb[i] = *reinterpret_cast<const float4*>(Bb + (size_t)row * oStride + c4 * 4);
        }
    };
    auto sts = [&](int buf) {
        char* base = smem + buf * STAGE_BYTES;
        #pragma unroll
        for (int i = 0; i < 4; ++i) {
            const int flat = i * 256 + tid;
            const int row = flat >> 3, c4 = flat & 7;
            const int byte = row * PITCH + c4 * 8;
            uint2 hi, lo;
            cvt2(ra[i], hi, lo);
            *reinterpret_cast<uint2*>(base + OFF_AHI + byte) = hi;
            *reinterpret_cast<uint2*>(base + OFF_ALO + byte) = lo;
            cvt2(rb[i], hi, lo);
            *reinterpret_cast<uint2*>(base + OFF_BHI + byte) = hi;
            *reinterpret_cast<uint2*>(base + OFF_BLO + byte) = lo;
        }
    };

    // per-lane ldmatrix byte offsets (conflict-free via 80B pitch)
    const uint32_t aByte = (uint32_t)((wm * 32 + (lane & 15)) * PITCH + (lane >> 4) * 16);
    const uint32_t bByte = (uint32_t)((wn * 64 + (lane & 15)) * PITCH + (lane >> 4) * 16);

    ldgl(0);
    sts(0);
    __syncthreads();

    for (int st = 0; st < 128; ++st) {
        if (st + 1 < 128) ldgl(st + 1);          // prefetch next stage -> regs

        const uint32_t bufb = sb + (uint32_t)((st & 1) * STAGE_BYTES);
        #pragma unroll
        for (int kk = 0; kk < 2; ++kk) {         // two k16 steps per 32-d stage
            uint32_t ah[2][4], al[2][4], bh[4][4], bl[4][4];
            #pragma unroll
            for (int mt = 0; mt < 2; ++mt) {
                ldm4(ah[mt], bufb + OFF_AHI + aByte + mt * (16 * PITCH) + kk * 32);
                ldm4(al[mt], bufb + OFF_ALO + aByte + mt * (16 * PITCH) + kk * 32);
            }
            #pragma unroll
            for (int nt = 0; nt < 4; ++nt) {
                ldm4(bh[nt], bufb + OFF_BHI + bByte + nt * (16 * PITCH) + kk * 32);
                ldm4(bl[nt], bufb + OFF_BLO + bByte + nt * (16 * PITCH) + kk * 32);
            }
            #pragma unroll
            for (int mt = 0; mt < 2; ++mt)
                #pragma unroll
                for (int nt = 0; nt < 4; ++nt) {
                    mma_bf16(acc[mt][nt * 2],     ah[mt], bh[nt][0], bh[nt][2]);
                    mma_bf16(acc[mt][nt * 2],     ah[mt], bl[nt][0], bl[nt][2]);
                    mma_bf16(acc[mt][nt * 2],     al[mt], bh[nt][0], bh[nt][2]);
                    mma_bf16(acc[mt][nt * 2 + 1], ah[mt], bh[nt][1], bh[nt][3]);
                    mma_bf16(acc[mt][nt * 2 + 1], ah[mt], bl[nt][1], bl[nt][3]);
                    mma_bf16(acc[mt][nt * 2 + 1], al[mt], bh[nt][1], bh[nt][3]);
                }
        }
        if (st + 1 < 128) sts((st + 1) & 1);
        __syncthreads();
    }

    // epilogue: write partials [map][chunk][o:128][s:256]
    float* dst = g_part + ((size_t)z * SLOT_STRIDE + chunk) * 32768;
    #pragma unroll
    for (int mt = 0; mt < 2; ++mt) {
        const int s0 = s_base + wm * 32 + mt * 16 + (lane >> 2);
        #pragma unroll
        for (int n8 = 0; n8 < 8; ++n8) {
            const int o = wn * 64 + (n8 >> 1) * 16 + (n8 & 1) * 8 + (lane & 3) * 2;
            dst[(size_t)o * 256 + s0]           = acc[mt][n8][0];
            dst[(size_t)(o + 1) * 256 + s0]     = acc[mt][n8][1];
            dst[(size_t)o * 256 + s0 + 8]       = acc[mt][n8][2];
            dst[(size_t)(o + 1) * 256 + s0 + 8] = acc[mt][n8][3];
        }
    }
}

// ---------------------------------------------------------------------------
// Reduce: sum the 4h chunks, + bias, max over p, ReLU, write (o, s, 1, 16)
// ---------------------------------------------------------------------------
__global__ void vrtconv_reduce(const float* __restrict__ b1,
                               const float* __restrict__ b2,
                               const float* __restrict__ b3,
                               float* __restrict__ out)
{
    const int t = blockIdx.x * blockDim.x + threadIdx.x;   // 32768 threads
    const int o = t >> 8;
    const int s = t & 255;

    float res[16];
    #pragma unroll
    for (int h_idx = 0; h_idx < 3; ++h_idx) {
        const int P    = 3 - h_idx;
        const int cnt  = (h_idx == 0) ? 6 : 5;
        const int base = (h_idx == 0) ? 0 : (h_idx == 1 ? 18 : 28);
        const int nch  = 4 * (h_idx + 1);
        const float* bb = (h_idx == 0) ? b1 : (h_idx == 1 ? b2 : b3);
        for (int jj = 0; jj < cnt; ++jj) {
            const float bias = bb[jj * 128 + o];
            float m = -1e30f;
            for (int pp = 0; pp < P; ++pp) {
                const int zmap = base + jj * P + pp;
                const float* q = g_part + ((size_t)zmap * SLOT_STRIDE) * 32768
                               + (size_t)o * 256 + s;
                float sum = 0.0f;
                for (int cc = 0; cc < nch; ++cc) sum += q[(size_t)cc * 32768];
                m = fmaxf(m, sum + bias);
            }
            res[h_idx + 3 * jj] = fmaxf(m, 0.0f);
        }
    }

    float4* po = reinterpret_cast<float4*>(out + ((size_t)o * 256 + s) * 16);
    po[0] = make_float4(res[0],  res[1],  res[2],  res[3]);
    po[1] = make_float4(res[4],  res[5],  res[6],  res[7]);
    po[2] = make_float4(res[8],  res[9],  res[10], res[11]);
    po[3] = make_float4(res[12], res[13], res[14], res[15]);
}

// ---------------------------------------------------------------------------
extern "C" void kernel_launch(void* const* d_in, const int* in_sizes, int n_in,
                              void* d_out, int out_size) {
    const float* Ec = (const float*)d_in[0];
    const float* W1 = (const float*)d_in[1];
    const float* W2 = (const float*)d_in[2];
    const float* W3 = (const float*)d_in[3];
    const float* b1 = (const float*)d_in[4];
    const float* b2 = (const float*)d_in[5];
    const float* b3 = (const float*)d_in[6];
    float* out = (float*)d_out;

    cudaFuncSetAttribute(vrtconv_gemm,
                         cudaFuncAttributeMaxDynamicSharedMemorySize, SMEM_BYTES);

    dim3 grid(212, 2);   // 424 equal CTAs = ~3 waves on 148 SMs
    vrtconv_gemm<<<grid, 256, SMEM_BYTES>>>(Ec, W1, W2, W3);
    vrtconv_reduce<<<128, 256>>>(b1, b2, b3, out);
}

// round 4
// speedup vs baseline: 1.6085x; 1.6085x over previous
#include <cuda_runtime.h>
#include <cuda_fp16.h>
#include <cstdint>

// ---------------------------------------------------------------------------
// Problem:
//   Ec : (128 chan, 256 s, 3 l, 128 d) f32
//   W1 : (6,128,128,1,128)  W2 : (5,128,128,2,128)  W3 : (5,128,128,3,128)
//   b1 : (6,128) b2 : (5,128) b3 : (5,128)
//   out: (128 o, 256 s, 1, 16 k) f32
// 33 conv maps: z<18 -> h=1 (kl=z/3, p=z%3); z<28 -> h=2; else h=3.
// GEMM per map: out[o,s] = sum_{a,c,d} Ec[a,s,p+c,d] * W[kl,o,a,c,d]
//   M=256(s), N=128(o), K=128*h*128.
// fp16 single-pass mma.sync (rel_err ~4e-4 < 1e-3): 1/3 the MMA work of the
// round-2 bf16 hi/lo 3-GEMM split. Split-K: chunks of 16 (a,c) pairs (K=2048)
// -> 424 uniform CTAs; each W element read exactly once.
// ---------------------------------------------------------------------------

#define NMAPS 33
#define SLOT_STRIDE 24            // max chunks per map = 8*h <= 24
__device__ float g_part[NMAPS * SLOT_STRIDE * 128 * 256];

#define PITCH 80                  // smem row pitch: 64B fp16 data + 16B pad
#define OFF_A 0                   // A: 256 rows
#define OFF_B (256 * PITCH)       // B: 128 rows
#define STAGE_BYTES (384 * PITCH) // 30720
#define SMEM_BYTES (2 * STAGE_BYTES)

// ---------------------------------------------------------------------------
__device__ __forceinline__ uint32_t smem_u32(const void* p) {
    uint32_t r;
    asm("{ .reg .u64 t; cvta.to.shared.u64 t, %1; cvt.u32.u64 %0, t; }"
        : "=r"(r) : "l"(p));
    return r;
}

__device__ __forceinline__ void ldm4(uint32_t (&r)[4], uint32_t addr) {
    asm volatile("ldmatrix.sync.aligned.m8n8.x4.shared.b16 {%0,%1,%2,%3}, [%4];"
        : "=r"(r[0]), "=r"(r[1]), "=r"(r[2]), "=r"(r[3]) : "r"(addr));
}

__device__ __forceinline__ void mma_fp16(float (&d)[4], const uint32_t (&a)[4],
                                         uint32_t b0, uint32_t b1) {
    asm volatile(
        "mma.sync.aligned.m16n8k16.row.col.f32.f16.f16.f32 "
        "{%0,%1,%2,%3}, {%4,%5,%6,%7}, {%8,%9}, {%0,%1,%2,%3};"
        : "+f"(d[0]), "+f"(d[1]), "+f"(d[2]), "+f"(d[3])
        : "r"(a[0]), "r"(a[1]), "r"(a[2]), "r"(a[3]), "r"(b0), "r"(b1));
}

// f32x4 -> fp16x4 (8 bytes)
__device__ __forceinline__ uint2 cvt4(float4 v) {
    __half2 h01 = __floats2half2_rn(v.x, v.y);
    __half2 h23 = __floats2half2_rn(v.z, v.w);
    uint2 r;
    r.x = *reinterpret_cast<uint32_t*>(&h01);
    r.y = *reinterpret_cast<uint32_t*>(&h23);
    return r;
}

// ---------------------------------------------------------------------------
// GEMM: grid(424). One CTA = one map z, one K-chunk of 16 (a,c) pairs
// (K = 2048), full M = 256 (s), full N = 128 (o). 256 threads, 8 warps,
// warp tile 64(s) x 64(o). 64 stages of k32, double-buffered fp16 smem.
// ---------------------------------------------------------------------------
__global__ __launch_bounds__(256, 1)
void vrtconv_gemm(const float* __restrict__ Ec, const float* __restrict__ W1,
                  const float* __restrict__ W2, const float* __restrict__ W3)
{
    extern __shared__ char smem[];
    const int tid  = threadIdx.x;
    const int lane = tid & 31;
    const int wid  = tid >> 5;
    const int wm   = wid & 3;      // 4 m-warps (64 s each)
    const int wn   = wid >> 2;     // 2 n-warps (64 o each)
    const uint32_t sb = smem_u32(smem);

    // job decode: j -> (z, chunk, h)
    const int j = blockIdx.x;
    int z, chunk, h;
    if (j < 144)      { z = j >> 3;                  chunk = j & 7;    h = 1; }
    else if (j < 304) { int t = j - 144; z = 18 + (t >> 4); chunk = t & 15; h = 2; }
    else              { int t = j - 304; z = 28 + t / 24;   chunk = t % 24; h = 3; }

    int kl, p; const float* W;
    if (h == 1)      { kl = z / 3;         p = z % 3;         W = W1; }
    else if (h == 2) { kl = (z - 18) >> 1; p = (z - 18) & 1;  W = W2; }
    else             { kl = z - 28;        p = 0;             W = W3; }

    const size_t oStride = (size_t)16384 * h;           // o-stride in W (f32)
    const float* Wk = W + (size_t)kl * 2097152 * (size_t)h;

    float acc[4][8][4];
    #pragma unroll
    for (int a = 0; a < 4; ++a)
        #pragma unroll
        for (int b = 0; b < 8; ++b)
            #pragma unroll
            for (int c = 0; c < 4; ++c) acc[a][b][c] = 0.0f;

    float4 ra[8], rb[4];

    // stage st: pair q = chunk*16 + (st>>2), d-block d0 = (st&3)*32
    auto ldgA = [&](int st) {
        const int q  = chunk * 16 + (st >> 2);
        int a, c;
        if (h == 1)      { a = q;      c = 0;     }
        else if (h == 2) { a = q >> 1; c = q & 1; }
        else             { a = q / 3;  c = q % 3; }
        const int d0 = (st & 3) * 32;
        const float* Ab = Ec + (size_t)a * 98304 + (size_t)(p + c) * 128 + d0;
        #pragma unroll
        for (int i = 0; i < 8; ++i) {
            const int flat = i * 256 + tid;
            const int row = flat >> 3, c4 = flat & 7;       // row: s in [0,256)
            ra[i] = *reinterpret_cast<const float4*>(Ab + (size_t)row * 384 + c4 * 4);
        }
    };
    auto ldgB = [&](int st) {
        const int q  = chunk * 16 + (st >> 2);
        int a, c;
        if (h == 1)      { a = q;      c = 0;     }
        else if (h == 2) { a = q >> 1; c = q & 1; }
        else             { a = q / 3;  c = q % 3; }
        const int d0 = (st & 3) * 32;
        const float* Bb = Wk + ((size_t)a * h + c) * 128 + d0;
        #pragma unroll
        for (int i = 0; i < 4; ++i) {
            const int flat = i * 256 + tid;
            const int row = flat >> 3, c4 = flat & 7;       // row: o in [0,128)
            rb[i] = *reinterpret_cast<const float4*>(Bb + (size_t)row * oStride + c4 * 4);
        }
    };
    auto stsA = [&](int buf) {
        char* base = smem + buf * STAGE_BYTES + OFF_A;
        #pragma unroll
        for (int i = 0; i < 8; ++i) {
            const int flat = i * 256 + tid;
            const int row = flat >> 3, c4 = flat & 7;
            *reinterpret_cast<uint2*>(base + row * PITCH + c4 * 8) = cvt4(ra[i]);
        }
    };
    auto stsB = [&](int buf) {
        char* base = smem + buf * STAGE_BYTES + OFF_B;
        #pragma unroll
        for (int i = 0; i < 4; ++i) {
            const int flat = i * 256 + tid;
            const int row = flat >> 3, c4 = flat & 7;
            *reinterpret_cast<uint2*>(base + row * PITCH + c4 * 8) = cvt4(rb[i]);
        }
    };

    // ldmatrix per-lane byte offsets (conflict-free: 80B pitch)
    const uint32_t aByte = (uint32_t)((wm * 64 + (lane & 15)) * PITCH + (lane >> 4) * 16);
    const uint32_t bByte = (uint32_t)((wn * 64 + (lane & 15)) * PITCH + (lane >> 4) * 16);

    ldgA(0); ldgB(0);
    stsA(0); stsB(0);
    __syncthreads();

    for (int st = 0; st < 64; ++st) {
        const int buf = st & 1;
        const uint32_t bufb = sb + (uint32_t)(buf * STAGE_BYTES);
        const bool more = (st + 1 < 64);

        if (more) ldgA(st + 1);

        // kk = 0
        {
            uint32_t af[4][4], bf[4][4];
            #pragma unroll
            for (int mt = 0; mt < 4; ++mt)
                ldm4(af[mt], bufb + OFF_A + aByte + mt * (16 * PITCH));
            #pragma unroll
            for (int nj = 0; nj < 4; ++nj)
                ldm4(bf[nj], bufb + OFF_B + bByte + nj * (16 * PITCH));
            #pragma unroll
            for (int mt = 0; mt < 4; ++mt)
                #pragma unroll
                for (int nj = 0; nj < 4; ++nj) {
                    mma_fp16(acc[mt][nj * 2],     af[mt], bf[nj][0], bf[nj][2]);
                    mma_fp16(acc[mt][nj * 2 + 1], af[mt], bf[nj][1], bf[nj][3]);
                }
        }

        if (more) { stsA(buf ^ 1); ldgB(st + 1); }

        // kk = 1 (cols 16..31 -> byte offset +32)
        {
            uint32_t af[4][4], bf[4][4];
            #pragma unroll
            for (int mt = 0; mt < 4; ++mt)
                ldm4(af[mt], bufb + OFF_A + aByte + mt * (16 * PITCH) + 32);
            #pragma unroll
            for (int nj = 0; nj < 4; ++nj)
                ldm4(bf[nj], bufb + OFF_B + bByte + nj * (16 * PITCH) + 32);
            #pragma unroll
            for (int mt = 0; mt < 4; ++mt)
                #pragma unroll
                for (int nj = 0; nj < 4; ++nj) {
                    mma_fp16(acc[mt][nj * 2],     af[mt], bf[nj][0], bf[nj][2]);
                    mma_fp16(acc[mt][nj * 2 + 1], af[mt], bf[nj][1], bf[nj][3]);
                }
        }

        if (more) stsB(buf ^ 1);
        __syncthreads();
    }

    // epilogue: partials [map][chunk][o:128][s:256]
    float* dst = g_part + ((size_t)z * SLOT_STRIDE + chunk) * 32768;
    #pragma unroll
    for (int mt = 0; mt < 4; ++mt) {
        const int s0 = wm * 64 + mt * 16 + (lane >> 2);
        #pragma unroll
        for (int n8 = 0; n8 < 8; ++n8) {
            const int o = wn * 64 + n8 * 8 + (lane & 3) * 2;
            dst[(size_t)o * 256 + s0]           = acc[mt][n8][0];
            dst[(size_t)(o + 1) * 256 + s0]     = acc[mt][n8][1];
            dst[(size_t)o * 256 + s0 + 8]       = acc[mt][n8][2];
            dst[(size_t)(o + 1) * 256 + s0 + 8] = acc[mt][n8][3];
        }
    }
}

// ---------------------------------------------------------------------------
// Reduce: sum the 8h chunks, + bias, max over p, ReLU, write (o, s, 1, 16)
// ---------------------------------------------------------------------------
__global__ void vrtconv_reduce(const float* __restrict__ b1,
                               const float* __restrict__ b2,
                               const float* __restrict__ b3,
                               float* __restrict__ out)
{
    const int t = blockIdx.x * blockDim.x + threadIdx.x;   // 32768 threads
    const int o = t >> 8;
    const int s = t & 255;

    float res[16];
    #pragma unroll
    for (int h_idx = 0; h_idx < 3; ++h_idx) {
        const int P    = 3 - h_idx;
        const int cnt  = (h_idx == 0) ? 6 : 5;
        const int base = (h_idx == 0) ? 0 : (h_idx == 1 ? 18 : 28);
        const int nch  = 8 * (h_idx + 1);
        const float* bb = (h_idx == 0) ? b1 : (h_idx == 1 ? b2 : b3);
        for (int jj = 0; jj < cnt; ++jj) {
            const float bias = bb[jj * 128 + o];
            float m = -1e30f;
            for (int pp = 0; pp < P; ++pp) {
                const int zmap = base + jj * P + pp;
                const float* q = g_part + ((size_t)zmap * SLOT_STRIDE) * 32768
                               + (size_t)o * 256 + s;
                float sum = 0.0f;
                for (int cc = 0; cc < nch; ++cc) sum += q[(size_t)cc * 32768];
                m = fmaxf(m, sum + bias);
            }
            res[h_idx + 3 * jj] = fmaxf(m, 0.0f);
        }
    }

    float4* po = reinterpret_cast<float4*>(out + ((size_t)o * 256 + s) * 16);
    po[0] = make_float4(res[0],  res[1],  res[2],  res[3]);
    po[1] = make_float4(res[4],  res[5],  res[6],  res[7]);
    po[2] = make_float4(res[8],  res[9],  res[10], res[11]);
    po[3] = make_float4(res[12], res[13], res[14], res[15]);
}

// ---------------------------------------------------------------------------
extern "C" void kernel_launch(void* const* d_in, const int* in_sizes, int n_in,
                              void* d_out, int out_size) {
    const float* Ec = (const float*)d_in[0];
    const float* W1 = (const float*)d_in[1];
    const float* W2 = (const float*)d_in[2];
    const float* W3 = (const float*)d_in[3];
    const float* b1 = (const float*)d_in[4];
    const float* b2 = (const float*)d_in[5];
    const float* b3 = (const float*)d_in[6];
    float* out = (float*)d_out;

    cudaFuncSetAttribute(vrtconv_gemm,
                         cudaFuncAttributeMaxDynamicSharedMemorySize, SMEM_BYTES);

    vrtconv_gemm<<<424, 256, SMEM_BYTES>>>(Ec, W1, W2, W3);
    vrtconv_reduce<<<128, 256>>>(b1, b2, b3, out);
}

// round 5
// speedup vs baseline: 1.9574x; 1.2170x over previous
#include <cuda_runtime.h>
#include <cuda_fp16.h>
#include <cstdint>

// ---------------------------------------------------------------------------
// Problem:
//   Ec : (128 chan, 256 s, 3 l, 128 d) f32
//   W1 : (6,128,128,1,128)  W2 : (5,128,128,2,128)  W3 : (5,128,128,3,128)
//   b1 : (6,128) b2 : (5,128) b3 : (5,128)
//   out: (128 o, 256 s, 1, 16 k) f32
// 33 conv maps: z<18 -> h=1 (kl=z/3, p=z%3); z<28 -> h=2; else h=3.
// GEMM per map: out[o,s] = sum_{a,c,d} Ec[a,s,p+c,d] * W[kl,o,a,c,d]
//   M=256(s), N=128(o), K=128*h*128.
// Pipeline: (1) convert W+Ec to fp16 once, (2) cp.async 4-stage GEMM with
// mma.sync m16n8k16 f32 accum, split-K into K=2048 chunks -> 424 CTAs,
// (3) chunk-sum reduce, (4) bias+maxpool+ReLU+layout.
// ---------------------------------------------------------------------------

#define NMAPS 33
#define SLOT_STRIDE 24            // max chunks per map = 8*h <= 24

// fp16 scratch: [W1H | W2H | W3H | EcH]
#define W1H_OFF 0
#define W2H_OFF 12582912
#define W3H_OFF 33554432
#define ECH_OFF 65011712
__device__ __half g_half[77594624];            // 155 MB
__device__ float  g_part[NMAPS * SLOT_STRIDE * 32768];  // 104 MB partials
__device__ float  g_sum[NMAPS * 32768];        // per-map summed conv

#define PITCH 80                  // smem row pitch: 64B fp16 data + 16B pad
#define OFF_A 0                   // A: 256 rows (s)
#define OFF_B (256 * PITCH)       // B: 128 rows (o)
#define STAGE_BYTES (384 * PITCH) // 30720
#define NSTAGE 4
#define SMEM_BYTES (NSTAGE * STAGE_BYTES)      // 122880

// ---------------------------------------------------------------------------
__device__ __forceinline__ uint32_t smem_u32(const void* p) {
    uint32_t r;
    asm("{ .reg .u64 t; cvta.to.shared.u64 t, %1; cvt.u32.u64 %0, t; }"
        : "=r"(r) : "l"(p));
    return r;
}

__device__ __forceinline__ void ldm4(uint32_t (&r)[4], uint32_t addr) {
    asm volatile("ldmatrix.sync.aligned.m8n8.x4.shared.b16 {%0,%1,%2,%3}, [%4];"
        : "=r"(r[0]), "=r"(r[1]), "=r"(r[2]), "=r"(r[3]) : "r"(addr));
}

__device__ __forceinline__ void mma_fp16(float (&d)[4], const uint32_t (&a)[4],
                                         uint32_t b0, uint32_t b1) {
    asm volatile(
        "mma.sync.aligned.m16n8k16.row.col.f32.f16.f16.f32 "
        "{%0,%1,%2,%3}, {%4,%5,%6,%7}, {%8,%9}, {%0,%1,%2,%3};"
        : "+f"(d[0]), "+f"(d[1]), "+f"(d[2]), "+f"(d[3])
        : "r"(a[0]), "r"(a[1]), "r"(a[2]), "r"(a[3]), "r"(b0), "r"(b1));
}

__device__ __forceinline__ void cpa16(uint32_t dst, const void* src) {
    asm volatile("cp.async.cg.shared.global [%0], [%1], 16;"
        :: "r"(dst), "l"(src));
}
#define CPA_COMMIT() asm volatile("cp.async.commit_group;" ::: "memory")
#define CPA_WAIT2()  asm volatile("cp.async.wait_group 2;"  ::: "memory")

// ---------------------------------------------------------------------------
// fp32 -> fp16 converter (grid-stride, float4 -> half4)
// ---------------------------------------------------------------------------
__global__ void vrtconv_cvt(const float4* __restrict__ src, size_t dst4, int n4)
{
    uint2* dst = reinterpret_cast<uint2*>(g_half) + dst4;
    for (int i = blockIdx.x * blockDim.x + threadIdx.x; i < n4;
         i += gridDim.x * blockDim.x) {
        float4 v = src[i];
        __half2 h01 = __floats2half2_rn(v.x, v.y);
        __half2 h23 = __floats2half2_rn(v.z, v.w);
        uint2 r;
        r.x = *reinterpret_cast<uint32_t*>(&h01);
        r.y = *reinterpret_cast<uint32_t*>(&h23);
        dst[i] = r;
    }
}

// ---------------------------------------------------------------------------
// GEMM: grid(424). One CTA = one map z, one K-chunk of 16 (a,c) pairs
// (K = 2048), full M=256(s), full N=128(o). 8 warps, warp tile 64x64.
// 64 stages of k32, 4-deep cp.async pipeline on fp16 data.
// ---------------------------------------------------------------------------
__global__ __launch_bounds__(256, 1)
void vrtconv_gemm()
{
    extern __shared__ char smem[];
    const int tid  = threadIdx.x;
    const int lane = tid & 31;
    const int wid  = tid >> 5;
    const int wm   = wid & 3;      // 4 m-warps (64 s each)
    const int wn   = wid >> 2;     // 2 n-warps (64 o each)
    const uint32_t sb = smem_u32(smem);

    // job decode: j -> (z, chunk, h)
    const int j = blockIdx.x;
    int z, chunk, h;
    if (j < 144)      { z = j >> 3;                  chunk = j & 7;    h = 1; }
    else if (j < 304) { int t = j - 144; z = 18 + (t >> 4); chunk = t & 15; h = 2; }
    else              { int t = j - 304; z = 28 + t / 24;   chunk = t % 24; h = 3; }

    int kl, p; size_t whbase;
    if (h == 1)      { kl = z / 3;         p = z % 3;        whbase = W1H_OFF; }
    else if (h == 2) { kl = (z - 18) >> 1; p = (z - 18) & 1; whbase = W2H_OFF; }
    else             { kl = z - 28;        p = 0;            whbase = W3H_OFF; }

    const size_t oStrideH = (size_t)16384 * h;      // o-stride in WH (halfs)
    const __half* WHk = g_half + whbase + (size_t)kl * 2097152 * (size_t)h;
    const __half* ecH = g_half + ECH_OFF;

    float acc[4][8][4];
    #pragma unroll
    for (int a = 0; a < 4; ++a)
        #pragma unroll
        for (int b = 0; b < 8; ++b)
            #pragma unroll
            for (int c = 0; c < 4; ++c) acc[a][b][c] = 0.0f;

    // stage st: pair q = chunk*16 + (st>>2), d-block d0 = (st&3)*32
    auto issue = [&](int st) {
        const int q = chunk * 16 + (st >> 2);
        int a, cl;
        if (h == 1)      { a = q;      cl = 0;     }
        else if (h == 2) { a = q >> 1; cl = q & 1; }
        else             { a = q / 3;  cl = q % 3; }
        const int d0 = (st & 3) * 32;
        const __half* Asrc = ecH + (size_t)a * 98304 + (size_t)(p + cl) * 128 + d0;
        const __half* Bsrc = WHk + (size_t)q * 128 + d0;
        const uint32_t sa = sb + (uint32_t)((st & 3) * STAGE_BYTES);
        #pragma unroll
        for (int i = 0; i < 4; ++i) {            // A: 256 rows x 4 chunks
            const int flat = i * 256 + tid;
            const int row = flat >> 2, c = flat & 3;
            cpa16(sa + OFF_A + row * PITCH + c * 16,
                  Asrc + (size_t)row * 384 + c * 8);
        }
        #pragma unroll
        for (int i = 0; i < 2; ++i) {            // B: 128 rows x 4 chunks
            const int flat = i * 256 + tid;
            const int row = flat >> 2, c = flat & 3;
            cpa16(sa + OFF_B + row * PITCH + c * 16,
                  Bsrc + (size_t)row * oStrideH + c * 8);
        }
    };

    // ldmatrix per-lane byte offsets (conflict-free: 80B pitch)
    const uint32_t aByte = (uint32_t)((wm * 64 + (lane & 15)) * PITCH + (lane >> 4) * 16);
    const uint32_t bByte = (uint32_t)((wn * 64 + (lane & 15)) * PITCH + (lane >> 4) * 16);

    issue(0); CPA_COMMIT();
    issue(1); CPA_COMMIT();
    issue(2); CPA_COMMIT();

    for (int st = 0; st < 64; ++st) {
        CPA_WAIT2();
        __syncthreads();

        const uint32_t bufb = sb + (uint32_t)((st & 3) * STAGE_BYTES);
        #pragma unroll
        for (int kk = 0; kk < 2; ++kk) {
            uint32_t af[4][4], bf[4][4];
            #pragma unroll
            for (int mt = 0; mt < 4; ++mt)
                ldm4(af[mt], bufb + OFF_A + aByte + mt * (16 * PITCH) + kk * 32);
            #pragma unroll
            for (int nj = 0; nj < 4; ++nj)
                ldm4(bf[nj], bufb + OFF_B + bByte + nj * (16 * PITCH) + kk * 32);
            #pragma unroll
            for (int mt = 0; mt < 4; ++mt)
                #pragma unroll
                for (int nj = 0; nj < 4; ++nj) {
                    mma_fp16(acc[mt][nj * 2],     af[mt], bf[nj][0], bf[nj][2]);
                    mma_fp16(acc[mt][nj * 2 + 1], af[mt], bf[nj][1], bf[nj][3]);
                }
        }

        if (st + 3 < 64) issue(st + 3);
        CPA_COMMIT();
    }

    // epilogue: partials [map][chunk][o:128][s:256]
    float* dst = g_part + ((size_t)z * SLOT_STRIDE + chunk) * 32768;
    #pragma unroll
    for (int mt = 0; mt < 4; ++mt) {
        const int s0 = wm * 64 + mt * 16 + (lane >> 2);
        #pragma unroll
        for (int n8 = 0; n8 < 8; ++n8) {
            const int o = wn * 64 + n8 * 8 + (lane & 3) * 2;
            dst[(size_t)o * 256 + s0]           = acc[mt][n8][0];
            dst[(size_t)(o + 1) * 256 + s0]     = acc[mt][n8][1];
            dst[(size_t)o * 256 + s0 + 8]       = acc[mt][n8][2];
            dst[(size_t)(o + 1) * 256 + s0 + 8] = acc[mt][n8][3];
        }
    }
}

// ---------------------------------------------------------------------------
// Reduce stage 1: sum the 8h chunks of each map -> g_sum[map][o][s]
// grid(1056) x 256: 32 blocks per map, float4 over s.
// ---------------------------------------------------------------------------
__global__ void vrtconv_sum()
{
    const int map = blockIdx.x >> 5;
    const int idx = (blockIdx.x & 31) * 256 + threadIdx.x;  // 0..8191
    const int o   = idx >> 6;
    const int s4  = (idx & 63) << 2;
    const int h   = (map < 18) ? 1 : (map < 28) ? 2 : 3;
    const int nch = 8 * h;

    const float* q = g_part + (size_t)map * SLOT_STRIDE * 32768
                   + (size_t)o * 256 + s4;
    float4 acc = make_float4(0.f, 0.f, 0.f, 0.f);
    for (int cc = 0; cc < nch; ++cc) {
        float4 v = *reinterpret_cast<const float4*>(q + (size_t)cc * 32768);
        acc.x += v.x; acc.y += v.y; acc.z += v.z; acc.w += v.w;
    }
    *reinterpret_cast<float4*>(g_sum + (size_t)map * 32768
                               + (size_t)o * 256 + s4) = acc;
}

// ---------------------------------------------------------------------------
// Reduce stage 2: + bias, max over p, ReLU, write (o, s, 1, 16)
// ---------------------------------------------------------------------------
__global__ void vrtconv_finish(const float* __restrict__ b1,
                               const float* __restrict__ b2,
                               const float* __restrict__ b3,
                               float* __restrict__ out)
{
    const int t = blockIdx.x * blockDim.x + threadIdx.x;   // 32768 threads
    const int o = t >> 8;
    const int s = t & 255;

    float res[16];
    #pragma unroll
    for (int h_idx = 0; h_idx < 3; ++h_idx) {
        const int P    = 3 - h_idx;
        const int cnt  = (h_idx == 0) ? 6 : 5;
        const int base = (h_idx == 0) ? 0 : (h_idx == 1 ? 18 : 28);
        const float* bb = (h_idx == 0) ? b1 : (h_idx == 1 ? b2 : b3);
        for (int jj = 0; jj < cnt; ++jj) {
            const float bias = bb[jj * 128 + o];
            float m = -1e30f;
            for (int pp = 0; pp < P; ++pp) {
                const int zmap = base + jj * P + pp;
                m = fmaxf(m, g_sum[(size_t)zmap * 32768 + (size_t)o * 256 + s] + bias);
            }
            res[h_idx + 3 * jj] = fmaxf(m, 0.0f);
        }
    }

    float4* po = reinterpret_cast<float4*>(out + ((size_t)o * 256 + s) * 16);
    po[0] = make_float4(res[0],  res[1],  res[2],  res[3]);
    po[1] = make_float4(res[4],  res[5],  res[6],  res[7]);
    po[2] = make_float4(res[8],  res[9],  res[10], res[11]);
    po[3] = make_float4(res[12], res[13], res[14], res[15]);
}

// ---------------------------------------------------------------------------
extern "C" void kernel_launch(void* const* d_in, const int* in_sizes, int n_in,
                              void* d_out, int out_size) {
    const float* Ec = (const float*)d_in[0];
    const float* W1 = (const float*)d_in[1];
    const float* W2 = (const float*)d_in[2];
    const float* W3 = (const float*)d_in[3];
    const float* b1 = (const float*)d_in[4];
    const float* b2 = (const float*)d_in[5];
    const float* b3 = (const float*)d_in[6];
    float* out = (float*)d_out;

    // 1) fp32 -> fp16 conversion (W1, W2, W3, Ec)
    vrtconv_cvt<<<1024, 256>>>((const float4*)W1, W1H_OFF / 4, 12582912 / 4);
    vrtconv_cvt<<<1024, 256>>>((const float4*)W2, W2H_OFF / 4, 20971520 / 4);
    vrtconv_cvt<<<1024, 256>>>((const float4*)W3, W3H_OFF / 4, 31457280 / 4);
    vrtconv_cvt<<<1024, 256>>>((const float4*)Ec, ECH_OFF / 4, 12582912 / 4);

    // 2) GEMMs
    cudaFuncSetAttribute(vrtconv_gemm,
                         cudaFuncAttributeMaxDynamicSharedMemorySize, SMEM_BYTES);
    vrtconv_gemm<<<424, 256, SMEM_BYTES>>>();

    // 3) chunk sums, 4) bias + maxpool + ReLU + layout
    vrtconv_sum<<<1056, 256>>>();
    vrtconv_finish<<<128, 256>>>(b1, b2, b3, out);
}